// round 3
// baseline (speedup 1.0000x reference)
#include <cuda_runtime.h>
#include <cuda_bf16.h>
#include <math.h>

// Problem constants
#define NN 50000
#define EE 800000
#define DD 256
#define HD 128

// ---------------- device scratch (no allocations allowed) ----------------
__device__ __align__(16) float g_h [NN * DD];   // h = x @ W
__device__ __align__(16) float g_h2[NN * DD];   // relu(agg + bias)
__device__ float g_asrc[NN];
__device__ float g_adst[NN];
__device__ int   g_src[EE];
__device__ int   g_dst[EE];
__device__ int   g_csr[EE];                     // src ids grouped by dst
__device__ int   g_deg[NN];
__device__ int   g_rowptr[NN + 1];
__device__ int   g_cursor[NN];
__device__ int   g_is64;

// ------- init: zero degree counters + att accumulators, detect dtype ------
__global__ void k_init(const int* ei32) {
    int i = blockIdx.x * blockDim.x + threadIdx.x;
    if (i < NN) {
        g_deg[i]  = 0;
        g_asrc[i] = 0.f;
        g_adst[i] = 0.f;
    }
    if (i == 0) {
        // int64 little-endian: high 32-bit words (odd int32 slots) are all 0.
        // For real int32 data, 128 consecutive node ids all being 0 is impossible.
        int all0 = 1;
        for (int j = 0; j < 128; j++) {
            if (ei32[2 * j + 1] != 0) { all0 = 0; break; }
        }
        g_is64 = all0;
    }
}

// ---------------- convert edges to int32 + count in-degrees --------------
__global__ void k_convert(const void* ei) {
    int i = blockIdx.x * blockDim.x + threadIdx.x;
    if (i >= EE) return;
    int s, d;
    if (g_is64) {
        const long long* p = (const long long*)ei;
        s = (int)p[i];
        d = (int)p[EE + i];
    } else {
        const int* p = (const int*)ei;
        s = p[i];
        d = p[EE + i];
    }
    g_src[i] = s;
    g_dst[i] = d;
    atomicAdd(&g_deg[d], 1);
}

// ---------------- single-block exclusive scan of degrees -----------------
__global__ void k_scan() {
    const int T = 1024;
    int t = threadIdx.x;
    const int per = (NN + T - 1) / T;
    int begin = t * per;
    int endi  = begin + per; if (endi > NN) endi = NN;

    int sum = 0;
    for (int i = begin; i < endi; i++) sum += g_deg[i];

    __shared__ int ss[T];
    ss[t] = sum;
    __syncthreads();
    for (int off = 1; off < T; off <<= 1) {
        int v = (t >= off) ? ss[t - off] : 0;
        __syncthreads();
        ss[t] += v;
        __syncthreads();
    }
    int run = (t > 0) ? ss[t - 1] : 0;   // exclusive prefix
    for (int i = begin; i < endi; i++) {
        g_rowptr[i] = run;
        g_cursor[i] = run;
        run += g_deg[i];
    }
    if (t == T - 1) g_rowptr[NN] = ss[T - 1];
}

// ---------------- scatter edge src ids into CSR slots ---------------------
__global__ void k_fill() {
    int i = blockIdx.x * blockDim.x + threadIdx.x;
    if (i >= EE) return;
    int d   = g_dst[i];
    int pos = atomicAdd(&g_cursor[d], 1);
    g_csr[pos] = g_src[i];
}

// ---------------- tiled fp32 GEMM, double-buffered smem -------------------
// BM=128 BN=128 BK=16, 8x8 per thread, 256 threads.
// FUSE: +bias, relu on output (gemm2).
// ATT : accumulate per-row dot with att_src/att_dst into g_asrc/g_adst (gemm1).
template <bool FUSE, bool ATT>
__device__ __forceinline__ void gemm_body(const float* __restrict__ A,
                                          const float* __restrict__ B,
                                          const float* __restrict__ bias,
                                          const float* __restrict__ att_s,
                                          const float* __restrict__ att_d,
                                          float* __restrict__ C,
                                          int M, int N, int K) {
    const int BM = 128, BN = 128, BK = 16, TM = 8, TN = 8;
    __shared__ float As[2][BK][BM];
    __shared__ float Bs[2][BK][BN];

    int tid = threadIdx.x;
    int rowBase = blockIdx.y * BM;
    int colBase = blockIdx.x * BN;

    // A tile loads: float4 along K; 64 rows per pass, 2 passes.
    int aRow  = tid >> 2;          // 0..63
    int aCol4 = (tid & 3) * 4;     // 0,4,8,12
    // B tile loads: float4 along N; 8 rows per pass, 2 passes.
    int bRow  = tid >> 5;          // 0..7
    int bCol4 = (tid & 31) * 4;

    int tx = tid & 15, ty = tid >> 4;

    float acc[TM][TN];
#pragma unroll
    for (int i = 0; i < TM; i++)
#pragma unroll
        for (int j = 0; j < TN; j++) acc[i][j] = 0.0f;

    // ---- load first tile into buffer 0 ----
    float4 pa[2], pb[2];
#pragma unroll
    for (int r = 0; r < 2; r++) {
        int row = rowBase + aRow + r * 64;
        pa[r] = make_float4(0.f, 0.f, 0.f, 0.f);
        if (row < M) pa[r] = *(const float4*)(A + (size_t)row * K + aCol4);
        pb[r] = *(const float4*)(B + (size_t)(bRow + r * 8) * N + colBase + bCol4);
    }
#pragma unroll
    for (int r = 0; r < 2; r++) {
        As[0][aCol4 + 0][aRow + r * 64] = pa[r].x;
        As[0][aCol4 + 1][aRow + r * 64] = pa[r].y;
        As[0][aCol4 + 2][aRow + r * 64] = pa[r].z;
        As[0][aCol4 + 3][aRow + r * 64] = pa[r].w;
        *(float4*)&Bs[0][bRow + r * 8][bCol4] = pb[r];
    }
    __syncthreads();

    int buf = 0;
    for (int k0 = 0; k0 < K; k0 += BK) {
        int nk = k0 + BK;
        // Prefetch next tile's global loads (issue before compute to hide latency)
        if (nk < K) {
#pragma unroll
            for (int r = 0; r < 2; r++) {
                int row = rowBase + aRow + r * 64;
                pa[r] = make_float4(0.f, 0.f, 0.f, 0.f);
                if (row < M) pa[r] = *(const float4*)(A + (size_t)row * K + nk + aCol4);
                pb[r] = *(const float4*)(B + (size_t)(nk + bRow + r * 8) * N + colBase + bCol4);
            }
        }

        // Compute on current buffer
#pragma unroll
        for (int kk = 0; kk < BK; kk++) {
            float ra[TM], rb[TN];
            *(float4*)&ra[0] = *(const float4*)&As[buf][kk][ty * TM];
            *(float4*)&ra[4] = *(const float4*)&As[buf][kk][ty * TM + 4];
            *(float4*)&rb[0] = *(const float4*)&Bs[buf][kk][tx * TN];
            *(float4*)&rb[4] = *(const float4*)&Bs[buf][kk][tx * TN + 4];
#pragma unroll
            for (int i = 0; i < TM; i++)
#pragma unroll
                for (int j = 0; j < TN; j++) acc[i][j] += ra[i] * rb[j];
        }

        // Store prefetched tile into the other buffer
        if (nk < K) {
            int nb = buf ^ 1;
#pragma unroll
            for (int r = 0; r < 2; r++) {
                As[nb][aCol4 + 0][aRow + r * 64] = pa[r].x;
                As[nb][aCol4 + 1][aRow + r * 64] = pa[r].y;
                As[nb][aCol4 + 2][aRow + r * 64] = pa[r].z;
                As[nb][aCol4 + 3][aRow + r * 64] = pa[r].w;
                *(float4*)&Bs[nb][bRow + r * 8][bCol4] = pb[r];
            }
            __syncthreads();
            buf = nb;
        }
    }

    // ---- write C tile ----
#pragma unroll
    for (int i = 0; i < TM; i++) {
        int row = rowBase + ty * TM + i;
        if (row >= M) continue;
#pragma unroll
        for (int j = 0; j < TN; j += 4) {
            int col = colBase + tx * TN + j;
            float4 v = make_float4(acc[i][j], acc[i][j + 1], acc[i][j + 2], acc[i][j + 3]);
            if (FUSE) {
                v.x = fmaxf(v.x + bias[col + 0], 0.f);
                v.y = fmaxf(v.y + bias[col + 1], 0.f);
                v.z = fmaxf(v.z + bias[col + 2], 0.f);
                v.w = fmaxf(v.w + bias[col + 3], 0.f);
            }
            *(float4*)(C + (size_t)row * N + col) = v;
        }
    }

    // ---- fused attention-scalar epilogue (gemm1 only) ----
    if (ATT) {
        float as[TN], ad[TN];
#pragma unroll
        for (int j = 0; j < TN; j++) {
            as[j] = att_s[colBase + tx * TN + j];
            ad[j] = att_d[colBase + tx * TN + j];
        }
#pragma unroll
        for (int i = 0; i < TM; i++) {
            float v1 = 0.f, v2 = 0.f;
#pragma unroll
            for (int j = 0; j < TN; j++) {
                v1 += acc[i][j] * as[j];
                v2 += acc[i][j] * ad[j];
            }
            // Reduce across the 16 tx lanes (xor offsets toggle lane bits 0-3
            // only, so each 16-lane half-warp reduces independently).
#pragma unroll
            for (int off = 8; off > 0; off >>= 1) {
                v1 += __shfl_xor_sync(0xffffffffu, v1, off);
                v2 += __shfl_xor_sync(0xffffffffu, v2, off);
            }
            if (tx == 0) {
                int row = rowBase + ty * TM + i;
                if (row < M) {
                    atomicAdd(&g_asrc[row], v1);
                    atomicAdd(&g_adst[row], v2);
                }
            }
        }
    }
}

__global__ __launch_bounds__(256) void k_gemm1(const float* __restrict__ x,
                                               const float* __restrict__ W,
                                               const float* __restrict__ att_s,
                                               const float* __restrict__ att_d) {
    gemm_body<false, true>(x, W, nullptr, att_s, att_d, g_h, NN, DD, DD);
}

__global__ __launch_bounds__(256) void k_gemm2(const float* __restrict__ Wp,
                                               const float* __restrict__ bp,
                                               float* __restrict__ out) {
    gemm_body<true, false>(g_h2, Wp, bp, nullptr, nullptr, out, NN, HD, DD);
}

// ---------------- gather-side online-softmax aggregation ------------------
// One warp per destination node. Lanes split the 256-dim feature (8 each).
__global__ void k_agg(const float* __restrict__ bias) {
    int gw   = (blockIdx.x * blockDim.x + threadIdx.x) >> 5;
    int lane = threadIdx.x & 31;
    if (gw >= NN) return;

    int start = g_rowptr[gw];
    int end   = g_rowptr[gw + 1];
    float adst = g_adst[gw];

    float m = -INFINITY, s = 0.f;
    float4 acc0 = make_float4(0.f, 0.f, 0.f, 0.f);
    float4 acc1 = make_float4(0.f, 0.f, 0.f, 0.f);

    for (int j = start; j < end; j++) {
        int src = g_csr[j];                        // warp-uniform load
        float e = g_asrc[src] + adst;
        e = (e > 0.f) ? e : 0.2f * e;              // LeakyReLU(0.2)
        if (e > m) {
            float sc = __expf(m - e);              // exp(-inf)=0 first time
            s *= sc;
            acc0.x *= sc; acc0.y *= sc; acc0.z *= sc; acc0.w *= sc;
            acc1.x *= sc; acc1.y *= sc; acc1.z *= sc; acc1.w *= sc;
            m = e;
        }
        float w = __expf(e - m);
        s += w;
        const float4* hp = (const float4*)g_h + (size_t)src * 64 + lane * 2;
        float4 h0 = hp[0], h1 = hp[1];
        acc0.x += w * h0.x; acc0.y += w * h0.y; acc0.z += w * h0.z; acc0.w += w * h0.w;
        acc1.x += w * h1.x; acc1.y += w * h1.y; acc1.z += w * h1.z; acc1.w += w * h1.w;
    }

    float inv = 1.0f / (s + 1e-16f);
    const float4* b4 = (const float4*)bias + lane * 2;
    float4 bb0 = b4[0], bb1 = b4[1];
    float4 o0, o1;
    o0.x = fmaxf(acc0.x * inv + bb0.x, 0.f);
    o0.y = fmaxf(acc0.y * inv + bb0.y, 0.f);
    o0.z = fmaxf(acc0.z * inv + bb0.z, 0.f);
    o0.w = fmaxf(acc0.w * inv + bb0.w, 0.f);
    o1.x = fmaxf(acc1.x * inv + bb1.x, 0.f);
    o1.y = fmaxf(acc1.y * inv + bb1.y, 0.f);
    o1.z = fmaxf(acc1.z * inv + bb1.z, 0.f);
    o1.w = fmaxf(acc1.w * inv + bb1.w, 0.f);
    float4* op = (float4*)g_h2 + (size_t)gw * 64 + lane * 2;
    op[0] = o0;
    op[1] = o1;
}

// ---------------- launch ---------------------------------------------------
extern "C" void kernel_launch(void* const* d_in, const int* in_sizes, int n_in,
                              void* d_out, int out_size) {
    const float* x        = (const float*)d_in[0];
    const void*  ei       = d_in[1];
    const float* W        = (const float*)d_in[2];
    const float* att_src  = (const float*)d_in[3];
    const float* att_dst  = (const float*)d_in[4];
    const float* bias     = (const float*)d_in[5];
    const float* Wp       = (const float*)d_in[6];
    const float* bp       = (const float*)d_in[7];
    float*       out      = (float*)d_out;

    // CSR build
    k_init<<<(NN + 255) / 256, 256>>>((const int*)ei);
    k_convert<<<(EE + 255) / 256, 256>>>(ei);
    k_scan<<<1, 1024>>>();
    k_fill<<<(EE + 255) / 256, 256>>>();

    // h = x @ W with fused a_src/a_dst epilogue
    k_gemm1<<<dim3(2, 391), 256>>>(x, W, att_src, att_dst);

    // segment softmax + aggregation + bias + relu -> g_h2
    k_agg<<<(NN * 32 + 255) / 256, 256>>>(bias);

    // out = relu(g_h2 @ Wp + bp)
    k_gemm2<<<dim3(1, 391), 256>>>(Wp, bp, out);

    (void)in_sizes; (void)n_in; (void)out_size;
}

// round 5
// speedup vs baseline: 1.6599x; 1.6599x over previous
#include <cuda_runtime.h>
#include <cuda_bf16.h>
#include <math.h>
#include <stdint.h>

// Problem constants
#define NN 50000
#define EE 800000
#define DD 256
#define HD 128

// ---------------- device scratch (no allocations allowed) ----------------
__device__ __align__(16) float g_h [NN * DD];   // h = x @ W
__device__ __align__(16) float g_h2[NN * DD];   // relu(agg + bias)
__device__ float g_asrc[NN];
__device__ float g_adst[NN];
__device__ int   g_src[EE];
__device__ int   g_dst[EE];
__device__ int   g_csr[EE];                     // src ids grouped by dst
__device__ int   g_deg[NN];
__device__ int   g_rowptr[NN + 1];
__device__ int   g_cursor[NN];
__device__ int   g_is64;

// ------- init: zero degree counters + att accumulators, detect dtype ------
__global__ void k_init(const int* ei32) {
    int i = blockIdx.x * blockDim.x + threadIdx.x;
    if (i < NN) {
        g_deg[i]  = 0;
        g_asrc[i] = 0.f;
        g_adst[i] = 0.f;
    }
    if (i == 0) {
        // int64 little-endian: high 32-bit words (odd int32 slots) are all 0.
        int all0 = 1;
        for (int j = 0; j < 128; j++) {
            if (ei32[2 * j + 1] != 0) { all0 = 0; break; }
        }
        g_is64 = all0;
    }
}

// ---------------- convert edges to int32 + count in-degrees --------------
__global__ void k_convert(const void* ei) {
    int i = blockIdx.x * blockDim.x + threadIdx.x;
    if (i >= EE) return;
    int s, d;
    if (g_is64) {
        const long long* p = (const long long*)ei;
        s = (int)p[i];
        d = (int)p[EE + i];
    } else {
        const int* p = (const int*)ei;
        s = p[i];
        d = p[EE + i];
    }
    g_src[i] = s;
    g_dst[i] = d;
    atomicAdd(&g_deg[d], 1);
}

// ---------------- single-block exclusive scan of degrees -----------------
__global__ void k_scan() {
    const int T = 1024;
    int t = threadIdx.x;
    const int per = (NN + T - 1) / T;
    int begin = t * per;
    int endi  = begin + per; if (endi > NN) endi = NN;

    int sum = 0;
    for (int i = begin; i < endi; i++) sum += g_deg[i];

    __shared__ int ss[T];
    ss[t] = sum;
    __syncthreads();
    for (int off = 1; off < T; off <<= 1) {
        int v = (t >= off) ? ss[t - off] : 0;
        __syncthreads();
        ss[t] += v;
        __syncthreads();
    }
    int run = (t > 0) ? ss[t - 1] : 0;   // exclusive prefix
    for (int i = begin; i < endi; i++) {
        g_rowptr[i] = run;
        g_cursor[i] = run;
        run += g_deg[i];
    }
    if (t == T - 1) g_rowptr[NN] = ss[T - 1];
}

// ---------------- scatter edge src ids into CSR slots ---------------------
__global__ void k_fill() {
    int i = blockIdx.x * blockDim.x + threadIdx.x;
    if (i >= EE) return;
    int d   = g_dst[i];
    int pos = atomicAdd(&g_cursor[d], 1);
    g_csr[pos] = g_src[i];
}

// ---------------- TF32 tensor-core GEMM -----------------------------------
// BM=128 BN=128 BK=16; 8 warps (4 along M x 2 along N), warp tile 32x64.
// mma.sync.m16n8k8 tf32, fp32 accumulate. Double-buffered smem.
// FUSE: +bias, relu (gemm2).  ATT: fused a_src/a_dst row-dot epilogue (gemm1).

__device__ __forceinline__ uint32_t f2tf32(float x) {
    uint32_t y;
    asm("cvt.rna.tf32.f32 %0, %1;" : "=r"(y) : "f"(x));
    return y;
}

__device__ __forceinline__ void mma_tf32(float* c, const uint32_t* a, const uint32_t* b) {
    asm volatile(
        "mma.sync.aligned.m16n8k8.row.col.f32.tf32.tf32.f32 "
        "{%0,%1,%2,%3}, {%4,%5,%6,%7}, {%8,%9}, {%0,%1,%2,%3};"
        : "+f"(c[0]), "+f"(c[1]), "+f"(c[2]), "+f"(c[3])
        : "r"(a[0]), "r"(a[1]), "r"(a[2]), "r"(a[3]), "r"(b[0]), "r"(b[1]));
}

template <bool FUSE, bool ATT>
__device__ __forceinline__ void gemm_tc(const float* __restrict__ A,
                                        const float* __restrict__ B,
                                        const float* __restrict__ bias,
                                        const float* __restrict__ att_s,
                                        const float* __restrict__ att_d,
                                        float* __restrict__ C,
                                        int M, int N, int K) {
    const int BM = 128, BKT = 16;
    __shared__ float As[2][BM][BKT + 4];   // stride 20: banks (4g+tig) distinct
    __shared__ float Bs[2][BKT][128 + 8];  // stride 136: banks (8k+n) distinct

    int tid  = threadIdx.x;
    int lane = tid & 31;
    int g    = lane >> 2;    // group id 0..7
    int tig  = lane & 3;     // thread in group
    int warp = tid >> 5;
    int warpM = (warp & 3) * 32;
    int warpN = (warp >> 2) * 64;

    int rowBase = blockIdx.y * BM;
    int colBase = blockIdx.x * 128;

    // global->reg staging (2 float4 each for A and B per thread)
    float4 pa[2], pb[2];

    auto loadTiles = [&](int k0) {
#pragma unroll
        for (int t = 0; t < 2; t++) {
            int slot = tid + t * 256;
            // A: 128 rows x 4 float4
            int ar = slot >> 2, ac4 = (slot & 3) << 2;
            int row = rowBase + ar;
            pa[t] = make_float4(0.f, 0.f, 0.f, 0.f);
            if (row < M) pa[t] = *(const float4*)(A + (size_t)row * K + k0 + ac4);
            // B: 16 rows x 32 float4
            int br = slot >> 5, bc4 = (slot & 31) << 2;
            pb[t] = *(const float4*)(B + (size_t)(k0 + br) * N + colBase + bc4);
        }
    };
    auto storeTiles = [&](int buf) {
#pragma unroll
        for (int t = 0; t < 2; t++) {
            int slot = tid + t * 256;
            int ar = slot >> 2, ac4 = (slot & 3) << 2;
            As[buf][ar][ac4 + 0] = __uint_as_float(f2tf32(pa[t].x));
            As[buf][ar][ac4 + 1] = __uint_as_float(f2tf32(pa[t].y));
            As[buf][ar][ac4 + 2] = __uint_as_float(f2tf32(pa[t].z));
            As[buf][ar][ac4 + 3] = __uint_as_float(f2tf32(pa[t].w));
            int br = slot >> 5, bc4 = (slot & 31) << 2;
            Bs[buf][br][bc4 + 0] = __uint_as_float(f2tf32(pb[t].x));
            Bs[buf][br][bc4 + 1] = __uint_as_float(f2tf32(pb[t].y));
            Bs[buf][br][bc4 + 2] = __uint_as_float(f2tf32(pb[t].z));
            Bs[buf][br][bc4 + 3] = __uint_as_float(f2tf32(pb[t].w));
        }
    };

    float c[2][8][4];
#pragma unroll
    for (int mi = 0; mi < 2; mi++)
#pragma unroll
        for (int ni = 0; ni < 8; ni++)
#pragma unroll
            for (int r = 0; r < 4; r++) c[mi][ni][r] = 0.f;

    loadTiles(0);
    storeTiles(0);
    __syncthreads();

    int buf = 0;
    for (int k0 = 0; k0 < K; k0 += BKT) {
        int nk = k0 + BKT;
        if (nk < K) loadTiles(nk);           // prefetch next tile

#pragma unroll
        for (int ks = 0; ks < 2; ks++) {     // two k=8 steps per BK=16 tile
            int kk = ks * 8;
            uint32_t a[2][4], b[8][2];
#pragma unroll
            for (int mi = 0; mi < 2; mi++) {
                int r0 = warpM + mi * 16 + g;
                a[mi][0] = __float_as_uint(As[buf][r0    ][kk + tig    ]);
                a[mi][1] = __float_as_uint(As[buf][r0 + 8][kk + tig    ]);
                a[mi][2] = __float_as_uint(As[buf][r0    ][kk + tig + 4]);
                a[mi][3] = __float_as_uint(As[buf][r0 + 8][kk + tig + 4]);
            }
#pragma unroll
            for (int ni = 0; ni < 8; ni++) {
                int cn = warpN + ni * 8 + g;
                b[ni][0] = __float_as_uint(Bs[buf][kk + tig    ][cn]);
                b[ni][1] = __float_as_uint(Bs[buf][kk + tig + 4][cn]);
            }
#pragma unroll
            for (int mi = 0; mi < 2; mi++)
#pragma unroll
                for (int ni = 0; ni < 8; ni++)
                    mma_tf32(c[mi][ni], a[mi], b[ni]);
        }

        if (nk < K) {
            buf ^= 1;
            storeTiles(buf);                 // write other buffer
            __syncthreads();
        }
    }

    // ---- write C ----
#pragma unroll
    for (int mi = 0; mi < 2; mi++) {
#pragma unroll
        for (int rr = 0; rr < 2; rr++) {
            int row = rowBase + warpM + mi * 16 + g + rr * 8;
            if (row < M) {
#pragma unroll
                for (int ni = 0; ni < 8; ni++) {
                    int col = colBase + warpN + ni * 8 + tig * 2;
                    float v0 = c[mi][ni][rr * 2 + 0];
                    float v1 = c[mi][ni][rr * 2 + 1];
                    if (FUSE) {
                        v0 = fmaxf(v0 + bias[col    ], 0.f);
                        v1 = fmaxf(v1 + bias[col + 1], 0.f);
                    }
                    *(float2*)(C + (size_t)row * N + col) = make_float2(v0, v1);
                }
            }
        }
    }

    // ---- fused attention-scalar epilogue (gemm1 only) ----
    if (ATT) {
#pragma unroll
        for (int mi = 0; mi < 2; mi++) {
#pragma unroll
            for (int rr = 0; rr < 2; rr++) {
                float v1 = 0.f, v2 = 0.f;
#pragma unroll
                for (int ni = 0; ni < 8; ni++) {
                    int col = colBase + warpN + ni * 8 + tig * 2;
                    float c0 = c[mi][ni][rr * 2 + 0];
                    float c1 = c[mi][ni][rr * 2 + 1];
                    v1 += c0 * att_s[col] + c1 * att_s[col + 1];
                    v2 += c0 * att_d[col] + c1 * att_d[col + 1];
                }
                // reduce across the 4-lane tig group (same row)
#pragma unroll
                for (int off = 1; off <= 2; off <<= 1) {
                    v1 += __shfl_xor_sync(0xffffffffu, v1, off);
                    v2 += __shfl_xor_sync(0xffffffffu, v2, off);
                }
                int row = rowBase + warpM + mi * 16 + g + rr * 8;
                if (tig == 0 && row < M) {
                    atomicAdd(&g_asrc[row], v1);
                    atomicAdd(&g_adst[row], v2);
                }
            }
        }
    }
}

__global__ __launch_bounds__(256) void k_gemm1(const float* __restrict__ x,
                                               const float* __restrict__ W,
                                               const float* __restrict__ att_s,
                                               const float* __restrict__ att_d) {
    gemm_tc<false, true>(x, W, nullptr, att_s, att_d, g_h, NN, DD, DD);
}

__global__ __launch_bounds__(256) void k_gemm2(const float* __restrict__ Wp,
                                               const float* __restrict__ bp,
                                               float* __restrict__ out) {
    gemm_tc<true, false>(g_h2, Wp, bp, nullptr, nullptr, out, NN, HD, DD);
}

// ---------------- gather-side online-softmax aggregation ------------------
// One warp per destination node. Lanes split the 256-dim feature (8 each).
__global__ void k_agg(const float* __restrict__ bias) {
    int gw   = (blockIdx.x * blockDim.x + threadIdx.x) >> 5;
    int lane = threadIdx.x & 31;
    if (gw >= NN) return;

    int start = g_rowptr[gw];
    int end   = g_rowptr[gw + 1];
    float adst = g_adst[gw];

    float m = -INFINITY, s = 0.f;
    float4 acc0 = make_float4(0.f, 0.f, 0.f, 0.f);
    float4 acc1 = make_float4(0.f, 0.f, 0.f, 0.f);

    for (int j = start; j < end; j++) {
        int src = g_csr[j];                        // warp-uniform load
        float e = g_asrc[src] + adst;
        e = (e > 0.f) ? e : 0.2f * e;              // LeakyReLU(0.2)
        if (e > m) {
            float sc = __expf(m - e);              // exp(-inf)=0 first time
            s *= sc;
            acc0.x *= sc; acc0.y *= sc; acc0.z *= sc; acc0.w *= sc;
            acc1.x *= sc; acc1.y *= sc; acc1.z *= sc; acc1.w *= sc;
            m = e;
        }
        float w = __expf(e - m);
        s += w;
        const float4* hp = (const float4*)g_h + (size_t)src * 64 + lane * 2;
        float4 h0 = hp[0], h1 = hp[1];
        acc0.x += w * h0.x; acc0.y += w * h0.y; acc0.z += w * h0.z; acc0.w += w * h0.w;
        acc1.x += w * h1.x; acc1.y += w * h1.y; acc1.z += w * h1.z; acc1.w += w * h1.w;
    }

    float inv = 1.0f / (s + 1e-16f);
    const float4* b4 = (const float4*)bias + lane * 2;
    float4 bb0 = b4[0], bb1 = b4[1];
    float4 o0, o1;
    o0.x = fmaxf(acc0.x * inv + bb0.x, 0.f);
    o0.y = fmaxf(acc0.y * inv + bb0.y, 0.f);
    o0.z = fmaxf(acc0.z * inv + bb0.z, 0.f);
    o0.w = fmaxf(acc0.w * inv + bb0.w, 0.f);
    o1.x = fmaxf(acc1.x * inv + bb1.x, 0.f);
    o1.y = fmaxf(acc1.y * inv + bb1.y, 0.f);
    o1.z = fmaxf(acc1.z * inv + bb1.z, 0.f);
    o1.w = fmaxf(acc1.w * inv + bb1.w, 0.f);
    float4* op = (float4*)g_h2 + (size_t)gw * 64 + lane * 2;
    op[0] = o0;
    op[1] = o1;
}

// ---------------- launch ---------------------------------------------------
extern "C" void kernel_launch(void* const* d_in, const int* in_sizes, int n_in,
                              void* d_out, int out_size) {
    const float* x        = (const float*)d_in[0];
    const void*  ei       = d_in[1];
    const float* W        = (const float*)d_in[2];
    const float* att_src  = (const float*)d_in[3];
    const float* att_dst  = (const float*)d_in[4];
    const float* bias     = (const float*)d_in[5];
    const float* Wp       = (const float*)d_in[6];
    const float* bp       = (const float*)d_in[7];
    float*       out      = (float*)d_out;

    // CSR build
    k_init<<<(NN + 255) / 256, 256>>>((const int*)ei);
    k_convert<<<(EE + 255) / 256, 256>>>(ei);
    k_scan<<<1, 1024>>>();
    k_fill<<<(EE + 255) / 256, 256>>>();

    // h = x @ W with fused a_src/a_dst epilogue (TF32 tensor cores)
    k_gemm1<<<dim3(2, 391), 256>>>(x, W, att_src, att_dst);

    // segment softmax + aggregation + bias + relu -> g_h2
    k_agg<<<(NN * 32 + 255) / 256, 256>>>(bias);

    // out = relu(g_h2 @ Wp + bp)  (TF32 tensor cores)
    k_gemm2<<<dim3(1, 391), 256>>>(Wp, bp, out);

    (void)in_sizes; (void)n_in; (void)out_size;
}